// round 6
// baseline (speedup 1.0000x reference)
#include <cuda_runtime.h>
#include <cstdint>

// Problem constants
#define BATCH 4
#define CIN   256
#define HDIM  64
#define WDIM  64
#define HW    4096          // 64*64
#define OUTC  256
#define KKPOS 9             // 3x3
#define CKDIM 2304          // CIN * 9
#define NOFF  27            // 3*K*K offset-conv output channels
#define NPIX  (BATCH * HW)  // 16384
#define NCHUNK 8            // channel-split factor for offset conv

// Fused GEMM config (mma.sync m16n8k8 tf32), warp-specialized
#define TM 256              // CTA M tile (ALL out channels)
#define TN 128              // CTA N tile (pixels)
#define TK 32               // K per pipeline chunk
#define NSTAGE 3
#define KCHUNKS (CKDIM / TK)                  // 72
#define A_FLOATS (TM * TK)                    // 8192
#define B_FLOATS (TN * TK)                    // 4096
#define STAGE_FLOATS (A_FLOATS + B_FLOATS)    // 12288 (48 KB)
#define REC_OFF (NSTAGE * STAGE_FLOATS)       // 36864 floats
// records: 1152 int4 + 1152 float4 = 9216 floats
#define MBAR_BYTE_OFF ((REC_OFF + 9216) * 4)  // 184320
#define GEMM_SMEM_BYTES (MBAR_BYTE_OFF + 64)  // 184384

#define CONS_T 512          // consumer threads (16 warps)
#define PROD_T 64           // producer threads (2 warps)
#define BLOCK_T (CONS_T + PROD_T)

__device__ __forceinline__ uint32_t smem_u32(const void* p) {
    uint32_t a;
    asm("{ .reg .u64 t; cvta.to.shared.u64 t, %1; cvt.u32.u64 %0, t; }" : "=r"(a) : "l"(p));
    return a;
}
__device__ __forceinline__ void cp16(uint32_t dst, const void* src) {
    asm volatile("cp.async.cg.shared.global [%0], [%1], 16;" :: "r"(dst), "l"(src));
}
__device__ __forceinline__ float to_tf32(float f) {
    uint32_t u;
    asm("cvt.rna.tf32.f32 %0, %1;" : "=r"(u) : "f"(f));
    return __uint_as_float(u);
}
__device__ __forceinline__ void mma_tf32(float* c, const uint32_t* a, const uint32_t* b) {
    asm volatile(
        "mma.sync.aligned.m16n8k8.row.col.f32.tf32.tf32.f32 "
        "{%0,%1,%2,%3}, {%4,%5,%6,%7}, {%8,%9}, {%0,%1,%2,%3};"
        : "+f"(c[0]), "+f"(c[1]), "+f"(c[2]), "+f"(c[3])
        : "r"(a[0]), "r"(a[1]), "r"(a[2]), "r"(a[3]), "r"(b[0]), "r"(b[1]));
}

#define MBAR_INIT(a, c)  asm volatile("mbarrier.init.shared.b64 [%0], %1;" :: "r"(a), "r"(c) : "memory")
#define MBAR_ARRIVE(a)   asm volatile("mbarrier.arrive.shared.b64 _, [%0];" :: "r"(a) : "memory")
#define MBAR_WAIT(a, p) do {                                                        \
    uint32_t _m = (a), _p = (p), _d;                                                \
    asm volatile("{\n\t.reg .pred q;\n\t"                                           \
        "mbarrier.try_wait.parity.acquire.cta.shared::cta.b64 q, [%1], %2;\n\t"     \
        "selp.b32 %0, 1, 0, q;\n\t}" : "=r"(_d) : "r"(_m), "r"(_p) : "memory");     \
    if (!_d) {                                                                      \
        asm volatile("{\n\t.reg .pred q;\n\tW%=:\n\t"                               \
            "mbarrier.try_wait.parity.acquire.cta.shared::cta.b64 q, [%0], %1, 0x989680;\n\t" \
            "@q bra.uni D%=;\n\tbra.uni W%=;\n\tD%=:\n\t}"                          \
            :: "r"(_m), "r"(_p) : "memory");                                        \
    } } while (0)

// ---------------------------------------------------------------------------
// Scratch (static __device__ arrays: allocation inside kernel_launch is banned)
// ---------------------------------------------------------------------------
__device__ float g_off_part[NCHUNK * NOFF * NPIX];   // 14.2 MB
__device__ int4   g_rec_idx[BATCH * KKPOS * HW];     // 2.36 MB
__device__ float4 g_rec_w  [BATCH * KKPOS * HW];     // 2.36 MB
__device__ float  g_wt[OUTC * CKDIM];                // 2.36 MB (tf32-rounded)

// ---------------------------------------------------------------------------
// Kernel 0: round GEMM weight to tf32 once per launch.
// ---------------------------------------------------------------------------
__global__ __launch_bounds__(256)
void wprep_kernel(const float* __restrict__ weight)
{
    int i = blockIdx.x * 256 + threadIdx.x;
    if (i < OUTC * CKDIM) g_wt[i] = to_tf32(weight[i]);
}

// ---------------------------------------------------------------------------
// Kernel 1a: offset conv partials. grid=(NPIX/128, NCHUNK).
// ---------------------------------------------------------------------------
__global__ __launch_bounds__(128)
void offset_part_kernel(const float* __restrict__ x,
                        const float* __restrict__ w_off)
{
    __shared__ float s_w[NOFF * 16 * KKPOS];

    const int gid = blockIdx.x * blockDim.x + threadIdx.x;
    const int b  = gid >> 12;
    const int hw = gid & 4095;
    const int y  = hw >> 6;
    const int xw = hw & 63;
    const int cbase = blockIdx.y * (CIN / NCHUNK);

    float acc[NOFF];
#pragma unroll
    for (int i = 0; i < NOFF; i++) acc[i] = 0.f;

    const float* xb = x + (size_t)b * CIN * HW;

    for (int sub = 0; sub < 2; sub++) {
        const int c0 = cbase + sub * 16;
        __syncthreads();
        for (int i = threadIdx.x; i < NOFF * 16 * KKPOS; i += blockDim.x) {
            int oc  = i / (16 * KKPOS);
            int rem = i - oc * (16 * KKPOS);
            s_w[i] = w_off[oc * (CIN * KKPOS) + c0 * KKPOS + rem];
        }
        __syncthreads();

        for (int cc = 0; cc < 16; cc++) {
            const float* xp = xb + (size_t)(c0 + cc) * HW;
            float v[9];
#pragma unroll
            for (int j = 0; j < 9; j++) {
                int dy = j / 3 - 1, dx = j % 3 - 1;
                int yy = y + dy, xx = xw + dx;
                v[j] = (yy >= 0 && yy < HDIM && xx >= 0 && xx < WDIM)
                         ? xp[yy * WDIM + xx] : 0.f;
            }
            const float* sw = &s_w[cc * KKPOS];
#pragma unroll
            for (int oc = 0; oc < NOFF; oc++) {
                float s = 0.f;
#pragma unroll
                for (int j = 0; j < 9; j++)
                    s += sw[oc * (16 * KKPOS) + j] * v[j];
                acc[oc] += s;
            }
        }
    }

#pragma unroll
    for (int oc = 0; oc < NOFF; oc++)
        g_off_part[(blockIdx.y * NOFF + oc) * NPIX + gid] = acc[oc];
}

// ---------------------------------------------------------------------------
// Kernel 1b: reduce partials + build sampling records.
// ---------------------------------------------------------------------------
__global__ __launch_bounds__(256)
void offset_rec_kernel(const float* __restrict__ b_off)
{
    const int gid = blockIdx.x * blockDim.x + threadIdx.x;
    const int b  = gid >> 12;
    const int hw = gid & 4095;
    const int y  = hw >> 6;
    const int xw = hw & 63;

    float acc[NOFF];
#pragma unroll
    for (int oc = 0; oc < NOFF; oc++) {
        float s = b_off[oc];
#pragma unroll
        for (int c = 0; c < NCHUNK; c++)
            s += g_off_part[(c * NOFF + oc) * NPIX + gid];
        acc[oc] = s;
    }

#pragma unroll
    for (int kp = 0; kp < KKPOS; kp++) {
        float dy = acc[2 * kp];
        float dx = acc[2 * kp + 1];
        float mask = 1.f / (1.f + __expf(-acc[18 + kp]));

        float py = (float)(y  - 1 + kp / 3) + dy;
        float px = (float)(xw - 1 + kp % 3) + dx;
        float y0f = floorf(py), x0f = floorf(px);
        float ly = py - y0f,   lx = px - x0f;
        int y0 = (int)y0f, x0 = (int)x0f;

        int4 idx; float4 wv;
        {
            int yy = y0, xx = x0;
            bool ok = (yy >= 0 && yy < HDIM && xx >= 0 && xx < WDIM);
            int yc = min(max(yy, 0), HDIM - 1), xc = min(max(xx, 0), WDIM - 1);
            idx.x = yc * WDIM + xc;
            wv.x = ok ? (1.f - ly) * (1.f - lx) * mask : 0.f;
        }
        {
            int yy = y0, xx = x0 + 1;
            bool ok = (yy >= 0 && yy < HDIM && xx >= 0 && xx < WDIM);
            int yc = min(max(yy, 0), HDIM - 1), xc = min(max(xx, 0), WDIM - 1);
            idx.y = yc * WDIM + xc;
            wv.y = ok ? (1.f - ly) * lx * mask : 0.f;
        }
        {
            int yy = y0 + 1, xx = x0;
            bool ok = (yy >= 0 && yy < HDIM && xx >= 0 && xx < WDIM);
            int yc = min(max(yy, 0), HDIM - 1), xc = min(max(xx, 0), WDIM - 1);
            idx.z = yc * WDIM + xc;
            wv.z = ok ? ly * (1.f - lx) * mask : 0.f;
        }
        {
            int yy = y0 + 1, xx = x0 + 1;
            bool ok = (yy >= 0 && yy < HDIM && xx >= 0 && xx < WDIM);
            int yc = min(max(yy, 0), HDIM - 1), xc = min(max(xx, 0), WDIM - 1);
            idx.w = yc * WDIM + xc;
            wv.w = ok ? ly * lx * mask : 0.f;
        }

        int r = ((b * KKPOS + kp) << 12) + hw;
        g_rec_idx[r] = idx;
        g_rec_w[r]   = wv;
    }
}

// ---------------------------------------------------------------------------
// Kernel 2 (fused, warp-specialized): gather + tf32 mma.sync GEMM.
// out[b][o][n] = sum_ck g_wt[o][ck] * val(n, ck) + bias[o]
// CTA: M=256 x N=128 pixels x K=2304. 576 threads:
//   warps 0-15  (512 thr): consumers — lds fragments + mma (4x4 grid, 64x32).
//   warps 16-17 ( 64 thr): producers — cp.async A + gather/STS B per stage.
// Handoff via mbarriers: full[s] (64 producer arrivals),
//                        empty[s] (16 elected consumer-warp arrivals).
// ---------------------------------------------------------------------------
__global__ __launch_bounds__(BLOCK_T, 1)
void gemm_fused_kernel(const float* __restrict__ x,
                       const float* __restrict__ bias,
                       float* __restrict__ out)
{
    extern __shared__ float sm[];
    const int tid = threadIdx.x;
    const int wid = tid >> 5;
    const int lid = tid & 31;
    const int n0  = blockIdx.x * TN;
    const int b   = n0 >> 12;
    const int hw0 = n0 & 4095;
    const float* xb = x + (size_t)b * CIN * HW;
    const uint32_t sbase = smem_u32(sm);

    int4*   s_idx = (int4*)  (sm + REC_OFF);
    float4* s_w   = (float4*)(sm + REC_OFF + 4608);

    if (tid == 0) {
#pragma unroll
        for (int s = 0; s < NSTAGE; s++) {
            MBAR_INIT(sbase + MBAR_BYTE_OFF + s * 8, PROD_T);        // full
            MBAR_INIT(sbase + MBAR_BYTE_OFF + 24 + s * 8, 16);       // empty
        }
    }
    // Preload all 9*128 sampling records for this CTA's pixels.
    for (int i = tid; i < KKPOS * TN; i += BLOCK_T) {
        int kp = i >> 7, n = i & 127;
        int r  = ((b * KKPOS + kp) << 12) + hw0 + n;
        s_idx[i] = g_rec_idx[r];
        s_w[i]   = g_rec_w[r];
    }
    __syncthreads();

    if (wid >= 16) {
        // ------------------------- PRODUCER -------------------------
        const int ptid = tid - CONS_T;    // 0..63
        for (int i = 0; i < KCHUNKS; i++) {
            const int s = i % NSTAGE, q = i / NSTAGE;
            if (i >= NSTAGE)
                MBAR_WAIT(sbase + MBAR_BYTE_OFF + 24 + s * 8, (q - 1) & 1);

            const int k0 = i * TK;
            // A: 2048 cp16 / 64 threads = 32 each
            uint32_t sa = sbase + (uint32_t)(s * STAGE_FLOATS) * 4;
#pragma unroll 8
            for (int it = 0; it < 32; it++) {
                int c = ptid + it * PROD_T;
                int m = c >> 3, kc = c & 7;
                cp16(sa + (uint32_t)(kc * TM + m) * 16,
                     g_wt + (size_t)m * CKDIM + k0 + kc * 4);
            }
            asm volatile("cp.async.commit_group;" ::: "memory");

            // B: 1024 float4 cells / 64 threads = 16 each (gather + STS)
            float* sb = sm + s * STAGE_FLOATS + A_FLOATS;
#pragma unroll 4
            for (int it = 0; it < 16; it++) {
                int p  = ptid + it * PROD_T;
                int n  = p & 127;
                int kc = p >> 7;
                float v[4];
#pragma unroll
                for (int qq = 0; qq < 4; qq++) {
                    int ck = k0 + kc * 4 + qq;
                    int c  = ck / KKPOS;
                    int kp = ck - c * KKPOS;
                    int4   id = s_idx[kp * TN + n];
                    float4 w  = s_w [kp * TN + n];
                    const float* xp = xb + (size_t)c * HW;
                    v[qq] = to_tf32(w.x * xp[id.x] + w.y * xp[id.y]
                                  + w.z * xp[id.z] + w.w * xp[id.w]);
                }
                *(float4*)&sb[(kc * TN + n) * 4] = make_float4(v[0], v[1], v[2], v[3]);
            }
            asm volatile("cp.async.wait_group 0;" ::: "memory");
            MBAR_ARRIVE(sbase + MBAR_BYTE_OFF + s * 8);
        }
    } else {
        // ------------------------- CONSUMER -------------------------
        const int g   = lid >> 2;      // group id 0..7
        const int t4  = lid & 3;       // thread-in-group
        const int wm  = wid & 3;       // M quarter (64 rows)
        const int wn  = wid >> 2;      // N quarter (32 cols)

        float acc[4][4][4];
#pragma unroll
        for (int i = 0; i < 4; i++)
#pragma unroll
            for (int j = 0; j < 4; j++)
#pragma unroll
                for (int q = 0; q < 4; q++) acc[i][j][q] = 0.f;

        for (int i = 0; i < KCHUNKS; i++) {
            const int s = i % NSTAGE, q = i / NSTAGE;
            MBAR_WAIT(sbase + MBAR_BYTE_OFF + s * 8, q & 1);

            const uint32_t* Au = (const uint32_t*)(sm + s * STAGE_FLOATS);
            const uint32_t* Bu = Au + A_FLOATS;

#pragma unroll
            for (int ks = 0; ks < 4; ks++) {
                const int kc0 = 2 * ks, kc1 = 2 * ks + 1;
                uint32_t af[4][4], bf[4][2];
#pragma unroll
                for (int ii = 0; ii < 4; ii++) {
                    int m = wm * 64 + ii * 16 + g;
                    af[ii][0] = Au[kc0 * (TM * 4) + m * 4 + t4];
                    af[ii][1] = Au[kc0 * (TM * 4) + (m + 8) * 4 + t4];
                    af[ii][2] = Au[kc1 * (TM * 4) + m * 4 + t4];
                    af[ii][3] = Au[kc1 * (TM * 4) + (m + 8) * 4 + t4];
                }
#pragma unroll
                for (int jj = 0; jj < 4; jj++) {
                    int n = wn * 32 + jj * 8 + g;
                    bf[jj][0] = Bu[kc0 * (TN * 4) + n * 4 + t4];
                    bf[jj][1] = Bu[kc1 * (TN * 4) + n * 4 + t4];
                }
#pragma unroll
                for (int ii = 0; ii < 4; ii++)
#pragma unroll
                    for (int jj = 0; jj < 4; jj++)
                        mma_tf32(acc[ii][jj], af[ii], bf[jj]);
            }

            if (lid == 0)
                MBAR_ARRIVE(sbase + MBAR_BYTE_OFF + 24 + s * 8);
        }

        // Epilogue: add bias, store (pixel block stays within one batch).
#pragma unroll
        for (int ii = 0; ii < 4; ii++) {
            int r0 = wm * 64 + ii * 16 + g;
            float bi0 = bias[r0], bi1 = bias[r0 + 8];
            float* p0 = out + ((size_t)(b * OUTC + r0)) * HW + hw0;
            float* p1 = p0 + (size_t)8 * HW;
#pragma unroll
            for (int jj = 0; jj < 4; jj++) {
                int col = wn * 32 + jj * 8 + 2 * t4;
                float2 v0 = make_float2(acc[ii][jj][0] + bi0, acc[ii][jj][1] + bi0);
                float2 v1 = make_float2(acc[ii][jj][2] + bi1, acc[ii][jj][3] + bi1);
                *(float2*)(p0 + col) = v0;
                *(float2*)(p1 + col) = v1;
            }
        }
    }
}

// ---------------------------------------------------------------------------
// Launch: inputs per metadata order: x, w_off, b_off, weight, bias
// ---------------------------------------------------------------------------
extern "C" void kernel_launch(void* const* d_in, const int* in_sizes, int n_in,
                              void* d_out, int out_size)
{
    const float* x      = (const float*)d_in[0];
    const float* w_off  = (const float*)d_in[1];
    const float* b_off  = (const float*)d_in[2];
    const float* weight = (const float*)d_in[3];
    const float* bias   = (const float*)d_in[4];
    float* out = (float*)d_out;

    cudaFuncSetAttribute(gemm_fused_kernel,
                         cudaFuncAttributeMaxDynamicSharedMemorySize,
                         GEMM_SMEM_BYTES);

    wprep_kernel<<<(OUTC * CKDIM + 255) / 256, 256>>>(weight);

    dim3 pgrid(NPIX / 128, NCHUNK);
    offset_part_kernel<<<pgrid, 128>>>(x, w_off);

    offset_rec_kernel<<<NPIX / 256, 256>>>(b_off);

    gemm_fused_kernel<<<NPIX / TN, BLOCK_T, GEMM_SMEM_BYTES>>>(x, bias, out);
}

// round 7
// speedup vs baseline: 1.1662x; 1.1662x over previous
#include <cuda_runtime.h>
#include <cstdint>

// Problem constants
#define BATCH 4
#define CIN   256
#define HDIM  64
#define WDIM  64
#define HW    4096          // 64*64
#define OUTC  256
#define KKPOS 9             // 3x3
#define CKDIM 2304          // CIN * 9
#define NOFF  27            // 3*K*K offset-conv output channels
#define NPIX  (BATCH * HW)  // 16384
#define NCHUNK 16           // channel-split factor for offset conv

// Fused GEMM config (mma.sync m16n8k8 tf32), 2 CTAs/SM
#define TM 128              // CTA M tile (out-channel half)
#define TN 128              // CTA N tile (pixels)
#define TK 32               // K per pipeline chunk
#define NSTAGE 2
#define KCHUNKS (CKDIM / TK)                  // 72
#define A_FLOATS (TM * TK)                    // 4096
#define B_FLOATS (TN * TK)                    // 4096
#define STAGE_FLOATS (A_FLOATS + B_FLOATS)    // 8192 (32 KB)
#define REC_OFF (NSTAGE * STAGE_FLOATS)       // 16384 floats (64 KB)
// records: 1152 int4 (4608 floats) + 1152 float4 (4608 floats) = 36 KB
#define GEMM_SMEM_BYTES ((REC_OFF + 2 * 4608) * 4)   // 102400 (100 KB)

__device__ __forceinline__ uint32_t smem_u32(const void* p) {
    uint32_t a;
    asm("{ .reg .u64 t; cvta.to.shared.u64 t, %1; cvt.u32.u64 %0, t; }" : "=r"(a) : "l"(p));
    return a;
}
__device__ __forceinline__ void cp16(uint32_t dst, const void* src) {
    asm volatile("cp.async.cg.shared.global [%0], [%1], 16;" :: "r"(dst), "l"(src));
}
__device__ __forceinline__ float to_tf32(float f) {
    uint32_t u;
    asm("cvt.rna.tf32.f32 %0, %1;" : "=r"(u) : "f"(f));
    return __uint_as_float(u);
}
__device__ __forceinline__ void mma_tf32(float* c, const uint32_t* a, const uint32_t* b) {
    asm volatile(
        "mma.sync.aligned.m16n8k8.row.col.f32.tf32.tf32.f32 "
        "{%0,%1,%2,%3}, {%4,%5,%6,%7}, {%8,%9}, {%0,%1,%2,%3};"
        : "+f"(c[0]), "+f"(c[1]), "+f"(c[2]), "+f"(c[3])
        : "r"(a[0]), "r"(a[1]), "r"(a[2]), "r"(a[3]), "r"(b[0]), "r"(b[1]));
}

// ---------------------------------------------------------------------------
// Scratch (static __device__ arrays: allocation inside kernel_launch is banned)
// ---------------------------------------------------------------------------
__device__ float g_off_part[NCHUNK * NOFF * NPIX];   // 28.3 MB
__device__ int4   g_rec_idx[BATCH * KKPOS * HW];     // 2.36 MB
__device__ float4 g_rec_w  [BATCH * KKPOS * HW];     // 2.36 MB
__device__ float  g_wt[OUTC * CKDIM];                // 2.36 MB (tf32-rounded)

// ---------------------------------------------------------------------------
// Kernel 0: round GEMM weight to tf32 once per launch.
// ---------------------------------------------------------------------------
__global__ __launch_bounds__(256)
void wprep_kernel(const float* __restrict__ weight)
{
    int i = blockIdx.x * 256 + threadIdx.x;
    if (i < OUTC * CKDIM) g_wt[i] = to_tf32(weight[i]);
}

// ---------------------------------------------------------------------------
// Kernel 1a: offset conv partials. grid=(NPIX/128, NCHUNK).
// Each CTA: 128 pixels x (CIN/NCHUNK = 16) channels -> partial acc[27].
// ---------------------------------------------------------------------------
__global__ __launch_bounds__(128)
void offset_part_kernel(const float* __restrict__ x,
                        const float* __restrict__ w_off)
{
    __shared__ float s_w[NOFF * 16 * KKPOS];

    const int gid = blockIdx.x * blockDim.x + threadIdx.x;
    const int b  = gid >> 12;
    const int hw = gid & 4095;
    const int y  = hw >> 6;
    const int xw = hw & 63;
    const int c0 = blockIdx.y * (CIN / NCHUNK);   // 16-channel slice

    float acc[NOFF];
#pragma unroll
    for (int i = 0; i < NOFF; i++) acc[i] = 0.f;

    const float* xb = x + (size_t)b * CIN * HW;

    for (int i = threadIdx.x; i < NOFF * 16 * KKPOS; i += blockDim.x) {
        int oc  = i / (16 * KKPOS);
        int rem = i - oc * (16 * KKPOS);          // cc*9 + j
        s_w[i] = w_off[oc * (CIN * KKPOS) + c0 * KKPOS + rem];
    }
    __syncthreads();

    for (int cc = 0; cc < 16; cc++) {
        const float* xp = xb + (size_t)(c0 + cc) * HW;
        float v[9];
#pragma unroll
        for (int j = 0; j < 9; j++) {
            int dy = j / 3 - 1, dx = j % 3 - 1;
            int yy = y + dy, xx = xw + dx;
            v[j] = (yy >= 0 && yy < HDIM && xx >= 0 && xx < WDIM)
                     ? xp[yy * WDIM + xx] : 0.f;
        }
        const float* sw = &s_w[cc * KKPOS];
#pragma unroll
        for (int oc = 0; oc < NOFF; oc++) {
            float s = 0.f;
#pragma unroll
            for (int j = 0; j < 9; j++)
                s += sw[oc * (16 * KKPOS) + j] * v[j];
            acc[oc] += s;
        }
    }

#pragma unroll
    for (int oc = 0; oc < NOFF; oc++)
        g_off_part[(blockIdx.y * NOFF + oc) * NPIX + gid] = acc[oc];
}

// ---------------------------------------------------------------------------
// Kernel 1b: reduce partials + build sampling records.
// ---------------------------------------------------------------------------
__global__ __launch_bounds__(256)
void offset_rec_kernel(const float* __restrict__ b_off)
{
    const int gid = blockIdx.x * blockDim.x + threadIdx.x;
    const int b  = gid >> 12;
    const int hw = gid & 4095;
    const int y  = hw >> 6;
    const int xw = hw & 63;

    float acc[NOFF];
#pragma unroll
    for (int oc = 0; oc < NOFF; oc++) {
        float s = b_off[oc];
#pragma unroll
        for (int c = 0; c < NCHUNK; c++)
            s += g_off_part[(c * NOFF + oc) * NPIX + gid];
        acc[oc] = s;
    }

#pragma unroll
    for (int kp = 0; kp < KKPOS; kp++) {
        float dy = acc[2 * kp];
        float dx = acc[2 * kp + 1];
        float mask = 1.f / (1.f + __expf(-acc[18 + kp]));

        float py = (float)(y  - 1 + kp / 3) + dy;
        float px = (float)(xw - 1 + kp % 3) + dx;
        float y0f = floorf(py), x0f = floorf(px);
        float ly = py - y0f,   lx = px - x0f;
        int y0 = (int)y0f, x0 = (int)x0f;

        int4 idx; float4 wv;
        {
            int yy = y0, xx = x0;
            bool ok = (yy >= 0 && yy < HDIM && xx >= 0 && xx < WDIM);
            int yc = min(max(yy, 0), HDIM - 1), xc = min(max(xx, 0), WDIM - 1);
            idx.x = yc * WDIM + xc;
            wv.x = ok ? (1.f - ly) * (1.f - lx) * mask : 0.f;
        }
        {
            int yy = y0, xx = x0 + 1;
            bool ok = (yy >= 0 && yy < HDIM && xx >= 0 && xx < WDIM);
            int yc = min(max(yy, 0), HDIM - 1), xc = min(max(xx, 0), WDIM - 1);
            idx.y = yc * WDIM + xc;
            wv.y = ok ? (1.f - ly) * lx * mask : 0.f;
        }
        {
            int yy = y0 + 1, xx = x0;
            bool ok = (yy >= 0 && yy < HDIM && xx >= 0 && xx < WDIM);
            int yc = min(max(yy, 0), HDIM - 1), xc = min(max(xx, 0), WDIM - 1);
            idx.z = yc * WDIM + xc;
            wv.z = ok ? ly * (1.f - lx) * mask : 0.f;
        }
        {
            int yy = y0 + 1, xx = x0 + 1;
            bool ok = (yy >= 0 && yy < HDIM && xx >= 0 && xx < WDIM);
            int yc = min(max(yy, 0), HDIM - 1), xc = min(max(xx, 0), WDIM - 1);
            idx.w = yc * WDIM + xc;
            wv.w = ok ? ly * lx * mask : 0.f;
        }

        int r = ((b * KKPOS + kp) << 12) + hw;
        g_rec_idx[r] = idx;
        g_rec_w[r]   = wv;
    }
}

// ---------------------------------------------------------------------------
// Kernel 2 (fused): gather + tf32 mma.sync GEMM, 2 CTAs/SM.
// out[b][o][n] = sum_ck g_wt[o][ck] * val(n, ck) + bias[o]
// CTA: M=128 x N=128 pixels x K=2304, 256 threads (8 warps, 2x4 warp grid,
// warp tile 64x32 — R4-verified mapping). Double-buffered (NSTAGE=2):
// per iter: wait A(i) -> sync (frees stage !s) -> cp.async A(i+1) ->
// MMA(i) -> gather/STS B(i+1). Cross-CTA overlap hides phase serialization.
// ---------------------------------------------------------------------------
__device__ __forceinline__ void fill_A(float* sm, int stage, int chunk,
                                       int tid, int m0)
{
    const int k0 = chunk * TK;
    uint32_t sa = smem_u32(sm + stage * STAGE_FLOATS);
    // 128 rows x 8 kc-chunks = 1024 cp16; 256 threads -> 4 each
#pragma unroll
    for (int it = 0; it < 4; it++) {
        int c = tid + it * 256;
        int m = c >> 3, kc = c & 7;
        cp16(sa + (uint32_t)(kc * TM + m) * 16,
             g_wt + (size_t)(m0 + m) * CKDIM + k0 + kc * 4);
    }
    asm volatile("cp.async.commit_group;" ::: "memory");
}

__device__ __forceinline__ void fill_B(float* sm, int stage, int chunk, int tid,
                                       const float* __restrict__ xb,
                                       const int4* s_idx, const float4* s_w)
{
    const int k0 = chunk * TK;
    float* sb = sm + stage * STAGE_FLOATS + A_FLOATS;
    // 128 pixels x 8 kc = 1024 float4 cells; 256 threads -> 4 each.
#pragma unroll
    for (int it = 0; it < 4; it++) {
        int p  = tid + it * 256;
        int n  = p & 127;
        int kc = p >> 7;
        float v[4];
#pragma unroll
        for (int q = 0; q < 4; q++) {
            int ck = k0 + kc * 4 + q;
            int c  = ck / KKPOS;
            int kp = ck - c * KKPOS;
            int4   id = s_idx[kp * TN + n];
            float4 w  = s_w [kp * TN + n];
            const float* xp = xb + (size_t)c * HW;
            v[q] = to_tf32(w.x * xp[id.x] + w.y * xp[id.y]
                         + w.z * xp[id.z] + w.w * xp[id.w]);
        }
        *(float4*)&sb[(kc * TN + n) * 4] = make_float4(v[0], v[1], v[2], v[3]);
    }
}

__global__ __launch_bounds__(256, 2)
void gemm_fused_kernel(const float* __restrict__ x,
                       const float* __restrict__ bias,
                       float* __restrict__ out)
{
    extern __shared__ float sm[];
    const int tid = threadIdx.x;
    const int wid = tid >> 5;
    const int lid = tid & 31;
    const int g   = lid >> 2;      // group id 0..7
    const int t4  = lid & 3;       // thread-in-group
    const int wm  = wid & 1;       // M half (64 rows)
    const int wn  = wid >> 1;      // N quarter (32 cols)
    const int n0  = blockIdx.x * TN;
    const int m0  = blockIdx.y * TM;
    const int b   = n0 >> 12;
    const int hw0 = n0 & 4095;
    const float* xb = x + (size_t)b * CIN * HW;

    int4*   s_idx = (int4*)  (sm + REC_OFF);
    float4* s_w   = (float4*)(sm + REC_OFF + 4608);

    // Preload all 9*128 sampling records for this CTA's pixels.
    for (int i = tid; i < KKPOS * TN; i += 256) {
        int kp = i >> 7, n = i & 127;
        int r  = ((b * KKPOS + kp) << 12) + hw0 + n;
        s_idx[i] = g_rec_idx[r];
        s_w[i]   = g_rec_w[r];
    }
    __syncthreads();

    float acc[4][4][4];
#pragma unroll
    for (int i = 0; i < 4; i++)
#pragma unroll
        for (int j = 0; j < 4; j++)
#pragma unroll
            for (int q = 0; q < 4; q++) acc[i][j][q] = 0.f;

    // Prologue: stage 0 gets chunk 0 (A async, B computed).
    fill_A(sm, 0, 0, tid, m0);
    fill_B(sm, 0, 0, tid, xb, s_idx, s_w);

    for (int i = 0; i < KCHUNKS; i++) {
        const int s = i & 1;
        asm volatile("cp.async.wait_group 0;" ::: "memory");  // A(i) complete
        __syncthreads();   // everyone done with chunk i-1 -> stage !s free;
                           // also makes B(i) STS visible to all warps

        if (i + 1 < KCHUNKS)
            fill_A(sm, s ^ 1, i + 1, tid, m0);   // async into freed stage

        const uint32_t* Au = (const uint32_t*)(sm + s * STAGE_FLOATS);
        const uint32_t* Bu = Au + A_FLOATS;

#pragma unroll
        for (int ks = 0; ks < 4; ks++) {
            const int kc0 = 2 * ks, kc1 = 2 * ks + 1;
            uint32_t af[4][4], bf[4][2];
#pragma unroll
            for (int ii = 0; ii < 4; ii++) {
                int m = wm * 64 + ii * 16 + g;
                af[ii][0] = Au[kc0 * (TM * 4) + m * 4 + t4];
                af[ii][1] = Au[kc0 * (TM * 4) + (m + 8) * 4 + t4];
                af[ii][2] = Au[kc1 * (TM * 4) + m * 4 + t4];
                af[ii][3] = Au[kc1 * (TM * 4) + (m + 8) * 4 + t4];
            }
#pragma unroll
            for (int jj = 0; jj < 4; jj++) {
                int n = wn * 32 + jj * 8 + g;
                bf[jj][0] = Bu[kc0 * (TN * 4) + n * 4 + t4];
                bf[jj][1] = Bu[kc1 * (TN * 4) + n * 4 + t4];
            }
#pragma unroll
            for (int ii = 0; ii < 4; ii++)
#pragma unroll
                for (int jj = 0; jj < 4; jj++)
                    mma_tf32(acc[ii][jj], af[ii], bf[jj]);
        }

        // Produce B(i+1) into the freed stage; next iter's sync publishes it.
        if (i + 1 < KCHUNKS)
            fill_B(sm, s ^ 1, i + 1, tid, xb, s_idx, s_w);
    }

    // Epilogue: add bias, store (pixel block stays within one batch).
#pragma unroll
    for (int ii = 0; ii < 4; ii++) {
        int r0 = m0 + wm * 64 + ii * 16 + g;
        float bi0 = bias[r0], bi1 = bias[r0 + 8];
        float* p0 = out + ((size_t)(b * OUTC + r0)) * HW + hw0;
        float* p1 = p0 + (size_t)8 * HW;
#pragma unroll
        for (int jj = 0; jj < 4; jj++) {
            int col = wn * 32 + jj * 8 + 2 * t4;
            float2 v0 = make_float2(acc[ii][jj][0] + bi0, acc[ii][jj][1] + bi0);
            float2 v1 = make_float2(acc[ii][jj][2] + bi1, acc[ii][jj][3] + bi1);
            *(float2*)(p0 + col) = v0;
            *(float2*)(p1 + col) = v1;
        }
    }
}

// ---------------------------------------------------------------------------
// Launch: inputs per metadata order: x, w_off, b_off, weight, bias
// ---------------------------------------------------------------------------
extern "C" void kernel_launch(void* const* d_in, const int* in_sizes, int n_in,
                              void* d_out, int out_size)
{
    const float* x      = (const float*)d_in[0];
    const float* w_off  = (const float*)d_in[1];
    const float* b_off  = (const float*)d_in[2];
    const float* weight = (const float*)d_in[3];
    const float* bias   = (const float*)d_in[4];
    float* out = (float*)d_out;

    cudaFuncSetAttribute(gemm_fused_kernel,
                         cudaFuncAttributeMaxDynamicSharedMemorySize,
                         GEMM_SMEM_BYTES);

    wprep_kernel<<<(OUTC * CKDIM + 255) / 256, 256>>>(weight);

    dim3 pgrid(NPIX / 128, NCHUNK);
    offset_part_kernel<<<pgrid, 128>>>(x, w_off);

    offset_rec_kernel<<<NPIX / 256, 256>>>(b_off);

    dim3 mgrid(NPIX / TN, OUTC / TM);   // 128 x 2
    gemm_fused_kernel<<<mgrid, 256, GEMM_SMEM_BYTES>>>(x, bias, out);
}

// round 8
// speedup vs baseline: 1.3552x; 1.1621x over previous
#include <cuda_runtime.h>
#include <cstdint>

// Problem constants
#define BATCH 4
#define CIN   256
#define HDIM  64
#define WDIM  64
#define HW    4096          // 64*64
#define OUTC  256
#define KKPOS 9             // 3x3
#define CKDIM 2304          // CIN * 9
#define NOFF  27            // 3*K*K offset-conv output channels
#define NPIX  (BATCH * HW)  // 16384
#define NCHUNK 8            // channel-split factor for offset conv

// Fused GEMM config (mma.sync m16n8k8 tf32)
#define TM 256              // CTA M tile (ALL out channels -> val computed once)
#define TN 128              // CTA N tile (pixels)
#define TK 32               // K per pipeline chunk
#define NSTAGE 3
#define KCHUNKS (CKDIM / TK)                  // 72
#define A_FLOATS (TM * TK)                    // 8192
#define B_FLOATS (TN * TK)                    // 4096
#define STAGE_FLOATS (A_FLOATS + B_FLOATS)    // 12288 (48 KB)
#define REC_OFF (NSTAGE * STAGE_FLOATS)       // float offset of record area
// record area: 1152 int4 (4608 floats) + 1152 float4 (4608 floats)
#define GEMM_SMEM_BYTES ((REC_OFF + 2 * 4608) * 4)   // 184320

__device__ __forceinline__ uint32_t smem_u32(const void* p) {
    uint32_t a;
    asm("{ .reg .u64 t; cvta.to.shared.u64 t, %1; cvt.u32.u64 %0, t; }" : "=r"(a) : "l"(p));
    return a;
}
__device__ __forceinline__ void cp16(uint32_t dst, const void* src) {
    asm volatile("cp.async.cg.shared.global [%0], [%1], 16;" :: "r"(dst), "l"(src));
}
__device__ __forceinline__ float to_tf32(float f) {
    uint32_t u;
    asm("cvt.rna.tf32.f32 %0, %1;" : "=r"(u) : "f"(f));
    return __uint_as_float(u);
}
__device__ __forceinline__ void mma_tf32(float* c, const uint32_t* a, const uint32_t* b) {
    asm volatile(
        "mma.sync.aligned.m16n8k8.row.col.f32.tf32.tf32.f32 "
        "{%0,%1,%2,%3}, {%4,%5,%6,%7}, {%8,%9}, {%0,%1,%2,%3};"
        : "+f"(c[0]), "+f"(c[1]), "+f"(c[2]), "+f"(c[3])
        : "r"(a[0]), "r"(a[1]), "r"(a[2]), "r"(a[3]), "r"(b[0]), "r"(b[1]));
}

// ---------------------------------------------------------------------------
// Scratch (static __device__ arrays: allocation inside kernel_launch is banned)
// ---------------------------------------------------------------------------
__device__ float g_off_part[NCHUNK * NOFF * NPIX];   // 14.2 MB
__device__ int4   g_rec_idx[BATCH * KKPOS * HW];     // 2.36 MB
__device__ float4 g_rec_w  [BATCH * KKPOS * HW];     // 2.36 MB
__device__ float  g_wt[OUTC * CKDIM];                // 2.36 MB (tf32-rounded)

// ---------------------------------------------------------------------------
// Kernel 0: round GEMM weight to tf32 once per launch.
// ---------------------------------------------------------------------------
__global__ __launch_bounds__(256)
void wprep_kernel(const float* __restrict__ weight)
{
    int i = blockIdx.x * 256 + threadIdx.x;
    if (i < OUTC * CKDIM) g_wt[i] = to_tf32(weight[i]);
}

// ---------------------------------------------------------------------------
// Kernel 1a: offset conv partials. grid=(NPIX/128, NCHUNK). (R5 config)
// ---------------------------------------------------------------------------
__global__ __launch_bounds__(128)
void offset_part_kernel(const float* __restrict__ x,
                        const float* __restrict__ w_off)
{
    __shared__ float s_w[NOFF * 16 * KKPOS];

    const int gid = blockIdx.x * blockDim.x + threadIdx.x;
    const int b  = gid >> 12;
    const int hw = gid & 4095;
    const int y  = hw >> 6;
    const int xw = hw & 63;
    const int cbase = blockIdx.y * (CIN / NCHUNK);

    float acc[NOFF];
#pragma unroll
    for (int i = 0; i < NOFF; i++) acc[i] = 0.f;

    const float* xb = x + (size_t)b * CIN * HW;

    for (int sub = 0; sub < 2; sub++) {
        const int c0 = cbase + sub * 16;
        __syncthreads();
        for (int i = threadIdx.x; i < NOFF * 16 * KKPOS; i += blockDim.x) {
            int oc  = i / (16 * KKPOS);
            int rem = i - oc * (16 * KKPOS);
            s_w[i] = w_off[oc * (CIN * KKPOS) + c0 * KKPOS + rem];
        }
        __syncthreads();

        for (int cc = 0; cc < 16; cc++) {
            const float* xp = xb + (size_t)(c0 + cc) * HW;
            float v[9];
#pragma unroll
            for (int j = 0; j < 9; j++) {
                int dy = j / 3 - 1, dx = j % 3 - 1;
                int yy = y + dy, xx = xw + dx;
                v[j] = (yy >= 0 && yy < HDIM && xx >= 0 && xx < WDIM)
                         ? xp[yy * WDIM + xx] : 0.f;
            }
            const float* sw = &s_w[cc * KKPOS];
#pragma unroll
            for (int oc = 0; oc < NOFF; oc++) {
                float s = 0.f;
#pragma unroll
                for (int j = 0; j < 9; j++)
                    s += sw[oc * (16 * KKPOS) + j] * v[j];
                acc[oc] += s;
            }
        }
    }

#pragma unroll
    for (int oc = 0; oc < NOFF; oc++)
        g_off_part[(blockIdx.y * NOFF + oc) * NPIX + gid] = acc[oc];
}

// ---------------------------------------------------------------------------
// Kernel 1b: reduce partials + build sampling records.
// ---------------------------------------------------------------------------
__global__ __launch_bounds__(256)
void offset_rec_kernel(const float* __restrict__ b_off)
{
    const int gid = blockIdx.x * blockDim.x + threadIdx.x;
    const int b  = gid >> 12;
    const int hw = gid & 4095;
    const int y  = hw >> 6;
    const int xw = hw & 63;

    float acc[NOFF];
#pragma unroll
    for (int oc = 0; oc < NOFF; oc++) {
        float s = b_off[oc];
#pragma unroll
        for (int c = 0; c < NCHUNK; c++)
            s += g_off_part[(c * NOFF + oc) * NPIX + gid];
        acc[oc] = s;
    }

#pragma unroll
    for (int kp = 0; kp < KKPOS; kp++) {
        float dy = acc[2 * kp];
        float dx = acc[2 * kp + 1];
        float mask = 1.f / (1.f + __expf(-acc[18 + kp]));

        float py = (float)(y  - 1 + kp / 3) + dy;
        float px = (float)(xw - 1 + kp % 3) + dx;
        float y0f = floorf(py), x0f = floorf(px);
        float ly = py - y0f,   lx = px - x0f;
        int y0 = (int)y0f, x0 = (int)x0f;

        int4 idx; float4 wv;
        {
            int yy = y0, xx = x0;
            bool ok = (yy >= 0 && yy < HDIM && xx >= 0 && xx < WDIM);
            int yc = min(max(yy, 0), HDIM - 1), xc = min(max(xx, 0), WDIM - 1);
            idx.x = yc * WDIM + xc;
            wv.x = ok ? (1.f - ly) * (1.f - lx) * mask : 0.f;
        }
        {
            int yy = y0, xx = x0 + 1;
            bool ok = (yy >= 0 && yy < HDIM && xx >= 0 && xx < WDIM);
            int yc = min(max(yy, 0), HDIM - 1), xc = min(max(xx, 0), WDIM - 1);
            idx.y = yc * WDIM + xc;
            wv.y = ok ? (1.f - ly) * lx * mask : 0.f;
        }
        {
            int yy = y0 + 1, xx = x0;
            bool ok = (yy >= 0 && yy < HDIM && xx >= 0 && xx < WDIM);
            int yc = min(max(yy, 0), HDIM - 1), xc = min(max(xx, 0), WDIM - 1);
            idx.z = yc * WDIM + xc;
            wv.z = ok ? ly * (1.f - lx) * mask : 0.f;
        }
        {
            int yy = y0 + 1, xx = x0 + 1;
            bool ok = (yy >= 0 && yy < HDIM && xx >= 0 && xx < WDIM);
            int yc = min(max(yy, 0), HDIM - 1), xc = min(max(xx, 0), WDIM - 1);
            idx.w = yc * WDIM + xc;
            wv.w = ok ? ly * lx * mask : 0.f;
        }

        int r = ((b * KKPOS + kp) << 12) + hw;
        g_rec_idx[r] = idx;
        g_rec_w[r]   = wv;
    }
}

// ---------------------------------------------------------------------------
// Kernel 2 (fused): gather + tf32 mma.sync GEMM (R5 skeleton + pipelined B).
// CTA: M=256 x N=128 pixels x K=2304, 512 threads (16 warps, 4x4 warp grid,
// warp tile 64x32). Per iteration:
//   sync -> cp.async A(i+2) -> ISSUE gathers cell0 of B(i+2)
//   -> MMA ks0,ks1 (covers LDG latency) -> combine+STS cell0, issue cell1
//   -> MMA ks2,ks3 -> combine+STS cell1.
// ---------------------------------------------------------------------------
__device__ __forceinline__ void fill_A(float* sm, int stage, int chunk, int tid)
{
    const int k0 = chunk * TK;
    uint32_t sa = smem_u32(sm + stage * STAGE_FLOATS);
#pragma unroll
    for (int it = 0; it < 4; it++) {
        int c = tid + it * 512;
        int m = c >> 3, kc = c & 7;
        cp16(sa + (uint32_t)(kc * TM + m) * 16,
             g_wt + (size_t)m * CKDIM + k0 + kc * 4);
    }
    asm volatile("cp.async.commit_group;" ::: "memory");
}

// Issue the 16 gather loads for one B cell (pixel n, kc chunk of 4 k-values).
__device__ __forceinline__ void gatherB_issue(int k0, int n, int kc,
                                              const float* __restrict__ xb,
                                              const int4* s_idx, float* v)
{
#pragma unroll
    for (int q = 0; q < 4; q++) {
        int ck = k0 + kc * 4 + q;
        int c  = ck / KKPOS;
        int kp = ck - c * KKPOS;
        int4 id = s_idx[kp * TN + n];
        const float* xp = xb + (size_t)c * HW;
        v[q * 4 + 0] = xp[id.x];
        v[q * 4 + 1] = xp[id.y];
        v[q * 4 + 2] = xp[id.z];
        v[q * 4 + 3] = xp[id.w];
    }
}

// Combine with bilinear weights and store the cell to smem.
__device__ __forceinline__ void gatherB_store(float* sb, int k0, int n, int kc,
                                              const float4* s_w, const float* v)
{
    float r[4];
#pragma unroll
    for (int q = 0; q < 4; q++) {
        int ck = k0 + kc * 4 + q;
        int c  = ck / KKPOS;
        int kp = ck - c * KKPOS;
        float4 w = s_w[kp * TN + n];
        r[q] = to_tf32(w.x * v[q * 4 + 0] + w.y * v[q * 4 + 1]
                     + w.z * v[q * 4 + 2] + w.w * v[q * 4 + 3]);
    }
    *(float4*)&sb[(kc * TN + n) * 4] = make_float4(r[0], r[1], r[2], r[3]);
}

__global__ __launch_bounds__(512, 1)
void gemm_fused_kernel(const float* __restrict__ x,
                       const float* __restrict__ bias,
                       float* __restrict__ out)
{
    extern __shared__ float sm[];
    const int tid = threadIdx.x;
    const int wid = tid >> 5;
    const int lid = tid & 31;
    const int g   = lid >> 2;      // group id 0..7
    const int t4  = lid & 3;       // thread-in-group
    const int wm  = wid & 3;       // M quarter (64 rows)
    const int wn  = wid >> 2;      // N quarter (32 cols)
    const int n0  = blockIdx.x * TN;
    const int b   = n0 >> 12;
    const int hw0 = n0 & 4095;
    const float* xb = x + (size_t)b * CIN * HW;

    int4*   s_idx = (int4*)  (sm + REC_OFF);
    float4* s_w   = (float4*)(sm + REC_OFF + 4608);

    // Preload all 9*128 sampling records for this CTA's pixels.
    for (int i = tid; i < KKPOS * TN; i += 512) {
        int kp = i >> 7, n = i & 127;
        int r  = ((b * KKPOS + kp) << 12) + hw0 + n;
        s_idx[i] = g_rec_idx[r];
        s_w[i]   = g_rec_w[r];
    }
    __syncthreads();

    // This thread's two B cells (fixed across chunks).
    const int cn0 = tid & 127,        ckc0 = tid >> 7;        // cell 0
    const int cn1 = cn0,              ckc1 = ckc0 + 4;        // cell 1

    float acc[4][4][4];
#pragma unroll
    for (int i = 0; i < 4; i++)
#pragma unroll
        for (int j = 0; j < 4; j++)
#pragma unroll
            for (int q = 0; q < 4; q++) acc[i][j][q] = 0.f;

    // Prologue: chunks 0,1 fully staged (A async, B computed immediately).
    {
        float v[16];
        for (int pf = 0; pf < 2; pf++) {
            fill_A(sm, pf, pf, tid);
            float* sb = sm + pf * STAGE_FLOATS + A_FLOATS;
            gatherB_issue(pf * TK, cn0, ckc0, xb, s_idx, v);
            gatherB_store(sb, pf * TK, cn0, ckc0, s_w, v);
            gatherB_issue(pf * TK, cn1, ckc1, xb, s_idx, v);
            gatherB_store(sb, pf * TK, cn1, ckc1, s_w, v);
        }
    }

    for (int i = 0; i < KCHUNKS; i++) {
        const int s = i % NSTAGE;
        if (i == KCHUNKS - 1)
            asm volatile("cp.async.wait_group 0;" ::: "memory");
        else
            asm volatile("cp.async.wait_group 1;" ::: "memory");
        __syncthreads();   // publishes B(i), frees stage (i+2)%NSTAGE

        const bool pre = (i + 2 < KCHUNKS);
        const int  ks2 = (i + 2) % NSTAGE;
        const int  kn0 = (i + 2) * TK;
        float* sbn = sm + ks2 * STAGE_FLOATS + A_FLOATS;

        if (pre)
            fill_A(sm, ks2, i + 2, tid);

        float v[16];
        if (pre)
            gatherB_issue(kn0, cn0, ckc0, xb, s_idx, v);   // LDGs in flight

        const uint32_t* Au = (const uint32_t*)(sm + s * STAGE_FLOATS);
        const uint32_t* Bu = Au + A_FLOATS;

        // ---- MMA ks0, ks1 (covers cell-0 gather latency) ----
#pragma unroll
        for (int ks = 0; ks < 2; ks++) {
            const int kc0 = 2 * ks, kc1 = 2 * ks + 1;
            uint32_t af[4][4], bf[4][2];
#pragma unroll
            for (int ii = 0; ii < 4; ii++) {
                int m = wm * 64 + ii * 16 + g;
                af[ii][0] = Au[kc0 * (TM * 4) + m * 4 + t4];
                af[ii][1] = Au[kc0 * (TM * 4) + (m + 8) * 4 + t4];
                af[ii][2] = Au[kc1 * (TM * 4) + m * 4 + t4];
                af[ii][3] = Au[kc1 * (TM * 4) + (m + 8) * 4 + t4];
            }
#pragma unroll
            for (int jj = 0; jj < 4; jj++) {
                int n = wn * 32 + jj * 8 + g;
                bf[jj][0] = Bu[kc0 * (TN * 4) + n * 4 + t4];
                bf[jj][1] = Bu[kc1 * (TN * 4) + n * 4 + t4];
            }
#pragma unroll
            for (int ii = 0; ii < 4; ii++)
#pragma unroll
                for (int jj = 0; jj < 4; jj++)
                    mma_tf32(acc[ii][jj], af[ii], bf[jj]);
        }

        if (pre) {
            gatherB_store(sbn, kn0, cn0, ckc0, s_w, v);    // combine + STS
            gatherB_issue(kn0, cn1, ckc1, xb, s_idx, v);   // cell-1 LDGs
        }

        // ---- MMA ks2, ks3 (covers cell-1 gather latency) ----
#pragma unroll
        for (int ks = 2; ks < 4; ks++) {
            const int kc0 = 2 * ks, kc1 = 2 * ks + 1;
            uint32_t af[4][4], bf[4][2];
#pragma unroll
            for (int ii = 0; ii < 4; ii++) {
                int m = wm * 64 + ii * 16 + g;
                af[ii][0] = Au[kc0 * (TM * 4) + m * 4 + t4];
                af[ii][1] = Au[kc0 * (TM * 4) + (m + 8) * 4 + t4];
                af[ii][2] = Au[kc1 * (TM * 4) + m * 4 + t4];
                af[ii][3] = Au[kc1 * (TM * 4) + (m + 8) * 4 + t4];
            }
#pragma unroll
            for (int jj = 0; jj < 4; jj++) {
                int n = wn * 32 + jj * 8 + g;
                bf[jj][0] = Bu[kc0 * (TN * 4) + n * 4 + t4];
                bf[jj][1] = Bu[kc1 * (TN * 4) + n * 4 + t4];
            }
#pragma unroll
            for (int ii = 0; ii < 4; ii++)
#pragma unroll
                for (int jj = 0; jj < 4; jj++)
                    mma_tf32(acc[ii][jj], af[ii], bf[jj]);
        }

        if (pre)
            gatherB_store(sbn, kn0, cn1, ckc1, s_w, v);
    }

    // Epilogue: add bias, store (pixel block stays within one batch).
#pragma unroll
    for (int ii = 0; ii < 4; ii++) {
        int r0 = wm * 64 + ii * 16 + g;
        float bi0 = bias[r0], bi1 = bias[r0 + 8];
        float* p0 = out + ((size_t)(b * OUTC + r0)) * HW + hw0;
        float* p1 = p0 + (size_t)8 * HW;
#pragma unroll
        for (int jj = 0; jj < 4; jj++) {
            int col = wn * 32 + jj * 8 + 2 * t4;
            float2 v0 = make_float2(acc[ii][jj][0] + bi0, acc[ii][jj][1] + bi0);
            float2 v1 = make_float2(acc[ii][jj][2] + bi1, acc[ii][jj][3] + bi1);
            *(float2*)(p0 + col) = v0;
            *(float2*)(p1 + col) = v1;
        }
    }
}

// ---------------------------------------------------------------------------
// Launch: inputs per metadata order: x, w_off, b_off, weight, bias
// ---------------------------------------------------------------------------
extern "C" void kernel_launch(void* const* d_in, const int* in_sizes, int n_in,
                              void* d_out, int out_size)
{
    const float* x      = (const float*)d_in[0];
    const float* w_off  = (const float*)d_in[1];
    const float* b_off  = (const float*)d_in[2];
    const float* weight = (const float*)d_in[3];
    const float* bias   = (const float*)d_in[4];
    float* out = (float*)d_out;

    cudaFuncSetAttribute(gemm_fused_kernel,
                         cudaFuncAttributeMaxDynamicSharedMemorySize,
                         GEMM_SMEM_BYTES);

    wprep_kernel<<<(OUTC * CKDIM + 255) / 256, 256>>>(weight);

    dim3 pgrid(NPIX / 128, NCHUNK);
    offset_part_kernel<<<pgrid, 128>>>(x, w_off);

    offset_rec_kernel<<<NPIX / 256, 256>>>(b_off);

    gemm_fused_kernel<<<NPIX / TN, 512, GEMM_SMEM_BYTES>>>(x, bias, out);
}